// round 17
// baseline (speedup 1.0000x reference)
#include <cuda_runtime.h>
#include <cuda_fp16.h>
#include <math.h>
#include <cstdint>

#define T_DIM 2048
#define H_DIM 4096
#define NHEADS 32
#define HD_DIM 128
#define FF_DIM 11008
#define QKV_N (3 * H_DIM)          // 12288
#define MLP_N (2 * FF_DIM)         // 22016 (interleaved w1|w2)
#define EPS_V 1e-6f

typedef __half h16;

// ===================== device scratch ======================================
__device__ float g_h   [(size_t)T_DIM * H_DIM];
__device__ float g_bqkv[QKV_N];

__device__ h16 g_xnh  [(size_t)T_DIM * H_DIM];
__device__ h16 g_atth [(size_t)T_DIM * H_DIM];
__device__ h16 g_yh   [(size_t)T_DIM * H_DIM];
__device__ h16 g_gh   [(size_t)T_DIM * FF_DIM];
__device__ h16 g_qkv16[(size_t)T_DIM * QKV_N];

// weights fp16, [K][N] row-major (same layout as input)
__device__ h16 g_wqkv[(size_t)H_DIM * QKV_N];
__device__ h16 g_woh [(size_t)H_DIM * H_DIM];
__device__ h16 g_w12 [(size_t)H_DIM * MLP_N];   // interleaved w1/w2
__device__ h16 g_wch [(size_t)FF_DIM * H_DIM];

// ===================== PTX helpers =========================================
__device__ __forceinline__ uint32_t smem_u32(const void* p) {
    uint32_t a;
    asm("{ .reg .u64 t; cvta.to.shared.u64 t, %1; cvt.u32.u64 %0, t; }"
        : "=r"(a) : "l"(p));
    return a;
}

#define CP_ASYNC16(dst, src) \
    asm volatile("cp.async.cg.shared.global [%0], [%1], 16;" :: "r"(dst), "l"(src))
#define CP_COMMIT() asm volatile("cp.async.commit_group;" ::: "memory")
#define CP_WAIT(n)  asm volatile("cp.async.wait_group %0;" :: "n"(n) : "memory")

__device__ __forceinline__ void ldsm_x4(uint32_t* r, uint32_t a) {
    asm volatile("ldmatrix.sync.aligned.m8n8.x4.shared.b16 {%0,%1,%2,%3}, [%4];"
        : "=r"(r[0]), "=r"(r[1]), "=r"(r[2]), "=r"(r[3]) : "r"(a));
}
__device__ __forceinline__ void ldsm_x4t(uint32_t* r, uint32_t a) {
    asm volatile("ldmatrix.sync.aligned.m8n8.x4.trans.shared.b16 {%0,%1,%2,%3}, [%4];"
        : "=r"(r[0]), "=r"(r[1]), "=r"(r[2]), "=r"(r[3]) : "r"(a));
}

__device__ __forceinline__ void mma_fp(float* d, const uint32_t* a,
                                       uint32_t b0, uint32_t b1) {
    asm volatile(
        "mma.sync.aligned.m16n8k16.row.col.f32.f16.f16.f32 "
        "{%0,%1,%2,%3}, {%4,%5,%6,%7}, {%8,%9}, {%0,%1,%2,%3};"
        : "+f"(d[0]), "+f"(d[1]), "+f"(d[2]), "+f"(d[3])
        : "r"(a[0]), "r"(a[1]), "r"(a[2]), "r"(a[3]), "r"(b0), "r"(b1));
}

__device__ __forceinline__ float silu_f(float g) {
    return g / (1.f + expf(-g));
}

// ===================== fp16 GEMM: C = A[M,K] @ B[K,N] (+bias) ================
// EPI: 0 = fp32 out (+resid), 1 = fp16 out, 3 = interleaved gated MLP.
#define BM 128
#define BN 128
#define GROWB 80
#define GTILE_A (128 * GROWB)
#define BROWB 272
#define GTILE_B (32 * BROWB)
#define STAGE_B (GTILE_A + GTILE_B)
#define GSMEM (4 * STAGE_B)            // 75776

template<int EPI>
__global__ __launch_bounds__(256, 2)
void gemm_f16(const h16* __restrict__ Ah, const h16* __restrict__ Bh,
              const float* __restrict__ bias, const float* __restrict__ resid,
              void* __restrict__ Cv, int Ntot, int K)
{
    extern __shared__ char dsm[];
    const int tid = threadIdx.x;
    const int wid = tid >> 5, lane = tid & 31;
    const int rowA0 = blockIdx.y * BM;
    const int colB0 = blockIdx.x * BN;
    const int nIter = K >> 5;
    const uint32_t sbase = smem_u32(dsm);

    auto load_stage = [&](int it) {
        const int s = it & 3;
        const size_t koff = (size_t)it * 32;
        const uint32_t sa = sbase + s * STAGE_B;
        const uint32_t sbt = sa + GTILE_A;
        #pragma unroll
        for (int i = 0; i < 2; i++) {
            int idx = tid + i * 256;
            int ra = idx >> 2, sega = idx & 3;
            CP_ASYNC16(sa + ra * GROWB + sega * 16,
                       Ah + (size_t)(rowA0 + ra) * K + koff + sega * 8);
            int rb = idx >> 4, segb = idx & 15;
            CP_ASYNC16(sbt + rb * BROWB + segb * 16,
                       Bh + (koff + rb) * (size_t)Ntot + colB0 + segb * 8);
        }
        CP_COMMIT();
    };

    const int m0 = (wid >> 1) * 32;
    const int n0 = (wid & 1) * 64;

    float acc[2][8][4];
    #pragma unroll
    for (int i = 0; i < 2; i++)
        #pragma unroll
        for (int j = 0; j < 8; j++)
            #pragma unroll
            for (int c = 0; c < 4; c++) acc[i][j][c] = 0.f;

    const int mi = lane >> 3, l7 = lane & 7;
    const uint32_t aoff = (uint32_t)((m0 + (mi & 1) * 8 + l7) * GROWB + (mi >> 1) * 16);
    const uint32_t boff = (uint32_t)(((mi & 1) * 8 + l7) * BROWB + (n0 + (mi >> 1) * 8) * 2);

    auto compute = [&](int it) {
        const uint32_t sa = sbase + (it & 3) * STAGE_B;
        const uint32_t sbt = sa + GTILE_A;
        #pragma unroll
        for (int kk = 0; kk < 2; kk++) {
            uint32_t ah0[4], ah1[4];
            ldsm_x4(ah0, sa + aoff + kk * 32);
            ldsm_x4(ah1, sa + aoff + 16 * GROWB + kk * 32);
            #pragma unroll
            for (int g = 0; g < 4; g++) {
                uint32_t bh[4];
                ldsm_x4t(bh, sbt + boff + kk * 16 * BROWB + g * 32);
                mma_fp(acc[0][2*g+0], ah0, bh[0], bh[1]);
                mma_fp(acc[0][2*g+1], ah0, bh[2], bh[3]);
                mma_fp(acc[1][2*g+0], ah1, bh[0], bh[1]);
                mma_fp(acc[1][2*g+1], ah1, bh[2], bh[3]);
            }
        }
    };

    load_stage(0); load_stage(1);

    for (int it = 0; it < nIter; it += 2) {
        if (it + 2 < nIter) load_stage(it + 2); else CP_COMMIT();
        if (it + 3 < nIter) load_stage(it + 3); else CP_COMMIT();
        CP_WAIT(2);
        __syncthreads();
        compute(it);
        compute(it + 1);
        __syncthreads();
    }

    const int l4 = lane >> 2, l2 = (lane & 3) * 2;
    #pragma unroll
    for (int mf = 0; mf < 2; mf++) {
        const int r = rowA0 + m0 + mf * 16 + l4;
        #pragma unroll
        for (int nf = 0; nf < 8; nf++) {
            const int c = colB0 + n0 + nf * 8 + l2;
            float2 v0 = make_float2(acc[mf][nf][0], acc[mf][nf][1]);
            float2 v1 = make_float2(acc[mf][nf][2], acc[mf][nf][3]);
            if (bias) {
                v0.x += bias[c]; v0.y += bias[c + 1];
                v1.x += bias[c]; v1.y += bias[c + 1];
            }
            if (EPI == 0) {
                if (resid) {
                    const float2 r0 = *(const float2*)&resid[(size_t)r * Ntot + c];
                    const float2 r1 = *(const float2*)&resid[(size_t)(r + 8) * Ntot + c];
                    v0.x += r0.x; v0.y += r0.y;
                    v1.x += r1.x; v1.y += r1.y;
                }
                float* C = (float*)Cv;
                *(float2*)&C[(size_t)r * Ntot + c] = v0;
                *(float2*)&C[(size_t)(r + 8) * Ntot + c] = v1;
            } else if (EPI == 1) {
                h16* C = (h16*)Cv;
                *(__half2*)&C[(size_t)r * Ntot + c] = __floats2half2_rn(v0.x, v0.y);
                *(__half2*)&C[(size_t)(r + 8) * Ntot + c] = __floats2half2_rn(v1.x, v1.y);
            } else { // EPI == 3
                const int No = Ntot >> 1;
                const int j = c >> 1;
                h16* C = (h16*)Cv;
                C[(size_t)r * No + j]       = __float2half_rn(v0.x * silu_f(v0.y));
                C[(size_t)(r + 8) * No + j] = __float2half_rn(v1.x * silu_f(v1.y));
            }
        }
    }
}

// ===================== tensor-core flash attention (fp16, occ-3) =============
// Single V buffer -> 61440 B smem -> 3 CTAs/SM (12 warps). Pipeline:
// [wait K_j,V_j] S (K dead) | sync | prefetch K_{j+1} | softmax+PV(V_j)
// | sync | load V_{j+1}.
#define AROW 272
#define PSROW 144
#define OFF_Q  0
#define OFF_K  (OFF_Q + 64 * AROW)
#define OFF_V  (OFF_K + 64 * AROW)
#define OFF_PS (OFF_V + 64 * AROW)
#define ATTN_SMEM (OFF_PS + 64 * PSROW)   // 61440

__global__ __launch_bounds__(128, 3)
void attn_mma_kernel(const h16* __restrict__ Q, const h16* __restrict__ K,
                     const h16* __restrict__ V, h16* __restrict__ Oh, int QS)
{
    extern __shared__ char asm_[];
    const uint32_t sb = smem_u32(asm_);
    const int qb = gridDim.x - 1 - blockIdx.x;   // longest first
    const int q0 = qb * 64;
    const int h  = blockIdx.y;
    const int tid = threadIdx.x;
    const int w = tid >> 5, lane = tid & 31;
    const int mi = lane >> 3, l7 = lane & 7;
    const size_t hoff = (size_t)h * HD_DIM;
    const int nIter = qb + 1;

    auto load_K = [&](int jj) {
        const int j0 = jj * 64;
        #pragma unroll
        for (int i = 0; i < 8; i++) {
            int idx = tid + i * 128;
            int r = idx >> 4, c = idx & 15;
            const size_t gsrc = (size_t)(j0 + r) * QS + hoff + c * 8;
            CP_ASYNC16(sb + OFF_K + r * AROW + c * 16, K + gsrc);
        }
        CP_COMMIT();
    };
    auto load_V = [&](int jj) {
        const int j0 = jj * 64;
        #pragma unroll
        for (int i = 0; i < 8; i++) {
            int idx = tid + i * 128;
            int r = idx >> 4, c = idx & 15;
            const size_t gsrc = (size_t)(j0 + r) * QS + hoff + c * 8;
            CP_ASYNC16(sb + OFF_V + r * AROW + c * 16, V + gsrc);
        }
        CP_COMMIT();
    };

    // prologue: Q, K0, V0
    #pragma unroll
    for (int i = 0; i < 8; i++) {
        int idx = tid + i * 128;
        int r = idx >> 4, c = idx & 15;
        const size_t gsrc = (size_t)(q0 + r) * QS + hoff + c * 8;
        CP_ASYNC16(sb + OFF_Q + r * AROW + c * 16, Q + gsrc);
    }
    CP_COMMIT();
    load_K(0);
    load_V(0);

    float oacc[16][4];
    #pragma unroll
    for (int f = 0; f < 16; f++)
        #pragma unroll
        for (int c = 0; c < 4; c++) oacc[f][c] = 0.f;
    float m0v = -1e30f, m1v = -1e30f, l0v = 0.f, l1v = 0.f;

    const uint32_t aq_off = (uint32_t)((w * 16 + (mi & 1) * 8 + l7) * AROW + (mi >> 1) * 16);
    const uint32_t bk_off = (uint32_t)(((mi >> 1) * 8 + l7) * AROW + (mi & 1) * 16);
    const uint32_t ps_off = (uint32_t)((w * 16 + (mi & 1) * 8 + l7) * PSROW + (mi >> 1) * 16);

    const int r0 = lane >> 2;
    const int gq0 = q0 + w * 16 + r0;
    const int gq1 = gq0 + 8;

    for (int jj = 0; jj < nIter; jj++) {
        const int j0 = jj * 64;
        CP_WAIT(0);               // this thread's K_jj (+V_jj) landed
        __syncthreads();          // all threads' -> visible

        // S = Q@K^T (Q pre-scaled into log2 domain)
        float sacc[8][4];
        #pragma unroll
        for (int f = 0; f < 8; f++)
            #pragma unroll
            for (int c = 0; c < 4; c++) sacc[f][c] = 0.f;

        #pragma unroll
        for (int ks = 0; ks < 8; ks++) {
            uint32_t a[4];
            ldsm_x4(a, sb + OFF_Q + aq_off + ks * 32);
            #pragma unroll
            for (int g = 0; g < 4; g++) {
                uint32_t b[4];
                ldsm_x4(b, sb + OFF_K + bk_off + g * 16 * AROW + ks * 32);
                mma_fp(sacc[2*g+0], a, b[0], b[1]);
                mma_fp(sacc[2*g+1], a, b[2], b[3]);
            }
        }

        if (j0 == q0) {
            #pragma unroll
            for (int f = 0; f < 8; f++) {
                int kvc = j0 + f * 8 + (lane & 3) * 2;
                if (kvc     > gq0) sacc[f][0] = -1e30f;
                if (kvc + 1 > gq0) sacc[f][1] = -1e30f;
                if (kvc     > gq1) sacc[f][2] = -1e30f;
                if (kvc + 1 > gq1) sacc[f][3] = -1e30f;
            }
        }

        float mx0 = -1e30f, mx1 = -1e30f;
        #pragma unroll
        for (int f = 0; f < 8; f++) {
            mx0 = fmaxf(mx0, fmaxf(sacc[f][0], sacc[f][1]));
            mx1 = fmaxf(mx1, fmaxf(sacc[f][2], sacc[f][3]));
        }
        mx0 = fmaxf(mx0, __shfl_xor_sync(0xffffffffu, mx0, 1));
        mx0 = fmaxf(mx0, __shfl_xor_sync(0xffffffffu, mx0, 2));
        mx1 = fmaxf(mx1, __shfl_xor_sync(0xffffffffu, mx1, 1));
        mx1 = fmaxf(mx1, __shfl_xor_sync(0xffffffffu, mx1, 2));
        const float mn0 = fmaxf(m0v, mx0), mn1 = fmaxf(m1v, mx1);
        float rs0 = 0.f, rs1 = 0.f;
        #pragma unroll
        for (int f = 0; f < 8; f++) {
            float p0 = exp2f(sacc[f][0] - mn0);
            float p1 = exp2f(sacc[f][1] - mn0);
            float p2 = exp2f(sacc[f][2] - mn1);
            float p3 = exp2f(sacc[f][3] - mn1);
            rs0 += p0 + p1; rs1 += p2 + p3;
            __half2 v01 = __floats2half2_rn(p0, p1);
            __half2 v23 = __floats2half2_rn(p2, p3);
            uint32_t col = (f * 8 + (lane & 3) * 2) * 2;
            *(uint32_t*)(asm_ + OFF_PS + (w * 16 + r0) * PSROW + col) = *(uint32_t*)&v01;
            *(uint32_t*)(asm_ + OFF_PS + (w * 16 + r0 + 8) * PSROW + col) = *(uint32_t*)&v23;
        }
        rs0 += __shfl_xor_sync(0xffffffffu, rs0, 1);
        rs0 += __shfl_xor_sync(0xffffffffu, rs0, 2);
        rs1 += __shfl_xor_sync(0xffffffffu, rs1, 1);
        rs1 += __shfl_xor_sync(0xffffffffu, rs1, 2);
        const float al0 = exp2f(m0v - mn0), al1 = exp2f(m1v - mn1);
        l0v = l0v * al0 + rs0; l1v = l1v * al1 + rs1;
        m0v = mn0; m1v = mn1;

        __syncthreads();          // K reads done by all; PS visible

        // prefetch next K (overlaps oacc rescale + PV)
        if (jj + 1 < nIter) load_K(jj + 1); else CP_COMMIT();

        #pragma unroll
        for (int f = 0; f < 16; f++) {
            oacc[f][0] *= al0; oacc[f][1] *= al0;
            oacc[f][2] *= al1; oacc[f][3] *= al1;
        }

        #pragma unroll
        for (int ks = 0; ks < 4; ks++) {
            uint32_t a[4];
            ldsm_x4(a, sb + OFF_PS + ps_off + ks * 32);
            #pragma unroll
            for (int g = 0; g < 8; g++) {
                uint32_t b[4];
                ldsm_x4t(b, sb + OFF_V + (ks * 16 + (mi & 1) * 8 + l7) * AROW
                               + (g * 16 + (mi >> 1) * 8) * 2);
                mma_fp(oacc[2*g+0], a, b[0], b[1]);
                mma_fp(oacc[2*g+1], a, b[2], b[3]);
            }
        }

        __syncthreads();          // V + PS reads done by all
        if (jj + 1 < nIter) load_V(jj + 1); else CP_COMMIT();
    }

    const float i0 = 1.f / l0v, i1 = 1.f / l1v;
    #pragma unroll
    for (int f = 0; f < 16; f++) {
        int col = h * HD_DIM + f * 8 + (lane & 3) * 2;
        __half2 hh0 = __floats2half2_rn(oacc[f][0] * i0, oacc[f][1] * i0);
        __half2 hh1 = __floats2half2_rn(oacc[f][2] * i1, oacc[f][3] * i1);
        *(__half2*)&Oh[(size_t)gq0 * H_DIM + col] = hh0;
        *(__half2*)&Oh[(size_t)gq1 * H_DIM + col] = hh1;
    }
}

// ===================== elementwise / conversion kernels =====================
__global__ void rmsnorm_f16_kernel(const float* __restrict__ x,
                                   const float* __restrict__ scale,
                                   h16* __restrict__ oh)
{
    int row = blockIdx.x;
    const float4* xr = (const float4*)(x + (size_t)row * H_DIM);
    float ss = 0.f;
    for (int i = threadIdx.x; i < H_DIM / 4; i += blockDim.x) {
        float4 v = xr[i];
        ss += v.x * v.x + v.y * v.y + v.z * v.z + v.w * v.w;
    }
    #pragma unroll
    for (int off = 16; off; off >>= 1) ss += __shfl_xor_sync(0xffffffffu, ss, off);
    __shared__ float red[32];
    int lane = threadIdx.x & 31, wid = threadIdx.x >> 5;
    if (lane == 0) red[wid] = ss;
    __syncthreads();
    if (wid == 0) {
        ss = (lane < (int)(blockDim.x >> 5)) ? red[lane] : 0.f;
        #pragma unroll
        for (int off = 16; off; off >>= 1) ss += __shfl_xor_sync(0xffffffffu, ss, off);
        if (lane == 0) red[0] = ss;
    }
    __syncthreads();
    float inv = rsqrtf(red[0] / (float)H_DIM + EPS_V);
    const float4* sc = (const float4*)scale;
    for (int i = threadIdx.x; i < H_DIM / 4; i += blockDim.x) {
        float4 v = xr[i], s = sc[i];
        __half2 lo = __floats2half2_rn(v.x * inv * s.x, v.y * inv * s.y);
        __half2 hi = __floats2half2_rn(v.z * inv * s.z, v.w * inv * s.w);
        uint2 pack = {*(uint32_t*)&lo, *(uint32_t*)&hi};
        ((uint2*)(oh + (size_t)row * H_DIM))[i] = pack;
    }
}

// streaming fp32 -> fp16, same [K][N] layout; output row stride OS.
__global__ void convert_f16_kernel(const float* __restrict__ W,
                                   h16* __restrict__ out,
                                   int N8, int OS, int total8)
{
    int i = blockIdx.x * blockDim.x + threadIdx.x;
    if (i >= total8) return;
    const float4* src = (const float4*)W + (size_t)i * 2;
    float4 a = src[0], b = src[1];
    __half2 h0 = __floats2half2_rn(a.x, a.y);
    __half2 h1 = __floats2half2_rn(a.z, a.w);
    __half2 h2 = __floats2half2_rn(b.x, b.y);
    __half2 h3 = __floats2half2_rn(b.z, b.w);
    int k = i / N8, n8 = i - k * N8;
    uint4 pack = {*(uint32_t*)&h0, *(uint32_t*)&h1, *(uint32_t*)&h2, *(uint32_t*)&h3};
    *(uint4*)(out + (size_t)k * OS + (size_t)n8 * 8) = pack;
}

// merged qkv convert: sections 0..2 pull from wq/wk/wv into g_wqkv columns.
__global__ void convert_qkv_kernel(const float* __restrict__ Wq,
                                   const float* __restrict__ Wk,
                                   const float* __restrict__ Wv,
                                   h16* __restrict__ out, int per8)
{
    int i = blockIdx.x * blockDim.x + threadIdx.x;
    if (i >= 3 * per8) return;
    int sec = i / per8, j = i - sec * per8;
    const float* W = (sec == 0) ? Wq : (sec == 1) ? Wk : Wv;
    const float4* src = (const float4*)W + (size_t)j * 2;
    float4 a = src[0], b = src[1];
    __half2 h0 = __floats2half2_rn(a.x, a.y);
    __half2 h1 = __floats2half2_rn(a.z, a.w);
    __half2 h2 = __floats2half2_rn(b.x, b.y);
    __half2 h3 = __floats2half2_rn(b.z, b.w);
    const int N8 = H_DIM / 8;
    int k = j / N8, n8 = j - k * N8;
    uint4 pack = {*(uint32_t*)&h0, *(uint32_t*)&h1, *(uint32_t*)&h2, *(uint32_t*)&h3};
    *(uint4*)(out + (size_t)k * QKV_N + sec * H_DIM + (size_t)n8 * 8) = pack;
}

// w1,w2 fp32 [K][FF] -> interleaved fp16 [K][2*FF]
__global__ void convert_pair_kernel(const float* __restrict__ W1,
                                    const float* __restrict__ W2,
                                    h16* __restrict__ out, int total8)
{
    int i = blockIdx.x * blockDim.x + threadIdx.x;
    if (i >= total8) return;
    const float4* s1 = (const float4*)W1 + (size_t)i * 2;
    const float4* s2 = (const float4*)W2 + (size_t)i * 2;
    float4 a1 = s1[0], b1 = s1[1];
    float4 a2 = s2[0], b2 = s2[1];
    __half2 p0 = __floats2half2_rn(a1.x, a2.x);
    __half2 p1 = __floats2half2_rn(a1.y, a2.y);
    __half2 p2 = __floats2half2_rn(a1.z, a2.z);
    __half2 p3 = __floats2half2_rn(a1.w, a2.w);
    __half2 p4 = __floats2half2_rn(b1.x, b2.x);
    __half2 p5 = __floats2half2_rn(b1.y, b2.y);
    __half2 p6 = __floats2half2_rn(b1.z, b2.z);
    __half2 p7 = __floats2half2_rn(b1.w, b2.w);
    uint4 lo = {*(uint32_t*)&p0, *(uint32_t*)&p1, *(uint32_t*)&p2, *(uint32_t*)&p3};
    uint4 hi = {*(uint32_t*)&p4, *(uint32_t*)&p5, *(uint32_t*)&p6, *(uint32_t*)&p7};
    uint4* dst = (uint4*)(out + (size_t)i * 16);
    dst[0] = lo;
    dst[1] = hi;
}

__global__ void bias_cat_kernel(const float* __restrict__ bq,
                                const float* __restrict__ bk,
                                const float* __restrict__ bv,
                                float* __restrict__ cat)
{
    int i = blockIdx.x * blockDim.x + threadIdx.x;
    if (i < H_DIM)          cat[i] = bq[i];
    else if (i < 2 * H_DIM) cat[i] = bk[i - H_DIM];
    else if (i < 3 * H_DIM) cat[i] = bv[i - 2 * H_DIM];
}

// RoPE in-place on fp16 q,k (row stride QS); q pre-scaled by log2(e)/sqrt(HD).
__global__ void rope_f16_kernel(h16* __restrict__ q, h16* __restrict__ k,
                                const int* __restrict__ pos, int QS)
{
    int idx = blockIdx.x * blockDim.x + threadIdx.x;
    if (idx >= T_DIM * NHEADS * (HD_DIM / 2)) return;
    int d  = idx & 63;
    int th = idx >> 6;
    int t  = th >> 5;
    int hh = th & 31;
    const float scaling = 0.08838834764831845f * 1.4426950408889634f;
    float invf = powf(10000.0f, -(float)d * (1.0f / 64.0f));
    float ang = (float)pos[t] * invf;
    float c, s;
    sincosf(ang, &s, &c);
    size_t base = (size_t)t * QS + hh * HD_DIM + d;
    float q1 = __half2float(q[base]), q2 = __half2float(q[base + 64]);
    q[base]      = __float2half_rn((q1 * c - q2 * s) * scaling);
    q[base + 64] = __float2half_rn((q2 * c + q1 * s) * scaling);
    float k1 = __half2float(k[base]), k2 = __half2float(k[base + 64]);
    k[base]      = __float2half_rn(k1 * c - k2 * s);
    k[base + 64] = __float2half_rn(k2 * c + k1 * s);
}

// ===================== launch ================================================
extern "C" void kernel_launch(void* const* d_in, const int* in_sizes, int n_in,
                              void* d_out, int out_size)
{
    (void)in_sizes; (void)n_in; (void)out_size;
    const int*   positions = (const int*)  d_in[0];
    const float* hidden    = (const float*)d_in[1];
    const float* ln1       = (const float*)d_in[2];
    const float* wq = (const float*)d_in[3];
    const float* bq = (const float*)d_in[4];
    const float* wk = (const float*)d_in[5];
    const float* bk = (const float*)d_in[6];
    const float* wv = (const float*)d_in[7];
    const float* bv = (const float*)d_in[8];
    const float* wo = (const float*)d_in[9];
    const float* ln2= (const float*)d_in[10];
    const float* w1 = (const float*)d_in[11];
    const float* w2 = (const float*)d_in[12];
    const float* wc = (const float*)d_in[13];
    float* out = (float*)d_out;

    float *hbuf, *bqkv;
    h16 *xnh, *atth, *yh, *gh, *qkv16;
    h16 *wqkv, *woh, *w12, *wch;
    cudaGetSymbolAddress((void**)&hbuf,  g_h);
    cudaGetSymbolAddress((void**)&bqkv,  g_bqkv);
    cudaGetSymbolAddress((void**)&xnh,   g_xnh);
    cudaGetSymbolAddress((void**)&atth,  g_atth);
    cudaGetSymbolAddress((void**)&yh,    g_yh);
    cudaGetSymbolAddress((void**)&gh,    g_gh);
    cudaGetSymbolAddress((void**)&qkv16, g_qkv16);
    cudaGetSymbolAddress((void**)&wqkv,  g_wqkv);
    cudaGetSymbolAddress((void**)&woh,   g_woh);
    cudaGetSymbolAddress((void**)&w12,   g_w12);
    cudaGetSymbolAddress((void**)&wch,   g_wch);

    cudaFuncSetAttribute((gemm_f16<0>), cudaFuncAttributeMaxDynamicSharedMemorySize, GSMEM);
    cudaFuncSetAttribute((gemm_f16<1>), cudaFuncAttributeMaxDynamicSharedMemorySize, GSMEM);
    cudaFuncSetAttribute((gemm_f16<3>), cudaFuncAttributeMaxDynamicSharedMemorySize, GSMEM);
    cudaFuncSetAttribute(attn_mma_kernel, cudaFuncAttributeMaxDynamicSharedMemorySize, ATTN_SMEM);

    // side stream + fork/join events (host resources; created once, reused)
    static cudaStream_t s_cvt = nullptr;
    static cudaEvent_t ev_fork = nullptr, ev_join = nullptr;
    if (s_cvt == nullptr) {
        cudaStreamCreateWithFlags(&s_cvt, cudaStreamNonBlocking);
        cudaEventCreateWithFlags(&ev_fork, cudaEventDisableTiming);
        cudaEventCreateWithFlags(&ev_join, cudaEventDisableTiming);
    }

    const int HH8 = H_DIM * H_DIM / 8;
    const int HF8 = H_DIM * FF_DIM / 8;

    // fork: wo/w12/wc converts on side stream
    cudaEventRecord(ev_fork, 0);
    cudaStreamWaitEvent(s_cvt, ev_fork, 0);
    convert_f16_kernel<<<(HH8 + 255) / 256, 256, 0, s_cvt>>>(wo, woh, H_DIM/8, H_DIM, HH8);
    convert_pair_kernel<<<(HF8 + 255) / 256, 256, 0, s_cvt>>>(w1, w2, w12, HF8);
    convert_f16_kernel<<<(HF8 + 255) / 256, 256, 0, s_cvt>>>(wc, wch, H_DIM/8, H_DIM, HF8);
    cudaEventRecord(ev_join, s_cvt);

    // main stream: critical path
    convert_qkv_kernel<<<(3 * HH8 + 255) / 256, 256>>>(wq, wk, wv, wqkv, HH8);
    bias_cat_kernel<<<(QKV_N + 255) / 256, 256>>>(bq, bk, bv, bqkv);

    // 1) x = rmsnorm(hidden, ln1) -> fp16
    rmsnorm_f16_kernel<<<T_DIM, 256>>>(hidden, ln1, xnh);

    // 2) fused qkv GEMM (fp16 out)
    dim3 gQKV(QKV_N / BN, T_DIM / BM);
    gemm_f16<1><<<gQKV, 256, GSMEM>>>(xnh, wqkv, bqkv, nullptr, qkv16, QKV_N, H_DIM);

    // 3) RoPE in place (q pre-scaled into log2 domain)
    rope_f16_kernel<<<(T_DIM * NHEADS * (HD_DIM / 2)) / 256, 256>>>(
        qkv16, qkv16 + H_DIM, positions, QKV_N);

    // 4) attention -> atth (fp16)
    attn_mma_kernel<<<dim3(T_DIM / 64, NHEADS), 128, ATTN_SMEM>>>(
        qkv16, qkv16 + H_DIM, qkv16 + 2 * H_DIM, atth, QKV_N);

    // join: weight converts must be done before wo GEMM
    cudaStreamWaitEvent(0, ev_join, 0);

    // 5) h = hidden + attn @ wo
    dim3 gH(H_DIM / BN, T_DIM / BM);
    gemm_f16<0><<<gH, 256, GSMEM>>>(atth, woh, nullptr, hidden, hbuf, H_DIM, H_DIM);

    // 6) y = rmsnorm(h, ln2) -> fp16
    rmsnorm_f16_kernel<<<T_DIM, 256>>>(hbuf, ln2, yh);

    // 7) fused gated MLP: gh = (y@w1) * silu(y@w2), single interleaved GEMM
    dim3 gF2(MLP_N / BN, T_DIM / BM);
    gemm_f16<3><<<gF2, 256, GSMEM>>>(yh, w12, nullptr, nullptr, gh, MLP_N, H_DIM);

    // 8) out = h + gh @ wc
    gemm_f16<0><<<gH, 256, GSMEM>>>(gh, wch, nullptr, hbuf, out, H_DIM, FF_DIM);
}